// round 2
// baseline (speedup 1.0000x reference)
#include <cuda_runtime.h>
#include <math.h>

// ---------------------------------------------------------------------------
// MultiScaleAdaptiveElasticityLossWithLame
//   d_in[0]: deformation_field (2,3,160,192,160) f32
//   d_in[1]: image             (2,1,160,192,160) f32
//   out: scalar f32 loss
// ---------------------------------------------------------------------------

#define D0 160
#define H0 192
#define W0 160
#define D1 80
#define H1 96
#define W1 80
#define D2 40
#define H2 48
#define W2 40

#define VOL0 (D0*H0*W0)   // 4,915,200
#define VOL1 (D1*H1*W1)   // 614,400
#define VOL2 (D2*H2*W2)   // 76,800

__device__ float g_def1[2*3*VOL1];
__device__ float g_img1[2*1*VOL1];
__device__ float g_def2[2*3*VOL2];
__device__ float g_img2[2*1*VOL2];
__device__ double g_acc[3];

__global__ void init_acc_kernel() {
    if (threadIdx.x < 3) g_acc[threadIdx.x] = 0.0;
}

// ---------------------------------------------------------------------------
// Combined trilinear downsample (align_corners=True) for def (6 planes) +
// img (2 planes). Compile-time dims -> cheap index math.
template<int Di, int Hi, int Wi, int Do, int Ho, int Wo>
__global__ void downsample_both(const float* __restrict__ def,
                                const float* __restrict__ img,
                                float* __restrict__ odef,
                                float* __restrict__ oimg,
                                float rD, float rH, float rW)
{
    constexpr int OVOL = Do * Ho * Wo;
    constexpr int IVOL = Di * Hi * Wi;
    int idx = blockIdx.x * blockDim.x + threadIdx.x;
    if (idx >= 8 * OVOL) return;

    int x = idx % Wo; int t = idx / Wo;
    int y = t % Ho;   t /= Ho;
    int z = t % Do;   int p = t / Do;     // plane 0..7

    const float* in; float* out;
    if (p < 6) { in = def + p * IVOL;        out = odef + p * OVOL; }
    else       { in = img + (p - 6) * IVOL;  out = oimg + (p - 6) * OVOL; }

    float cz = (float)z * rD;
    float cy = (float)y * rH;
    float cx = (float)x * rW;
    int z0 = min((int)floorf(cz), Di - 1);
    int y0 = min((int)floorf(cy), Hi - 1);
    int x0 = min((int)floorf(cx), Wi - 1);
    float wz = cz - (float)z0;
    float wy = cy - (float)y0;
    float wx = cx - (float)x0;
    int z1 = min(z0 + 1, Di - 1);
    int y1 = min(y0 + 1, Hi - 1);
    int x1 = min(x0 + 1, Wi - 1);

    const float* pz0 = in + z0 * (Hi * Wi);
    const float* pz1 = in + z1 * (Hi * Wi);
    int oy0 = y0 * Wi, oy1 = y1 * Wi;

    float v000 = __ldg(pz0 + oy0 + x0), v001 = __ldg(pz0 + oy0 + x1);
    float v010 = __ldg(pz0 + oy1 + x0), v011 = __ldg(pz0 + oy1 + x1);
    float v100 = __ldg(pz1 + oy0 + x0), v101 = __ldg(pz1 + oy0 + x1);
    float v110 = __ldg(pz1 + oy1 + x0), v111 = __ldg(pz1 + oy1 + x1);

    float a00 = v000 * (1.f - wx) + v001 * wx;
    float a01 = v010 * (1.f - wx) + v011 * wx;
    float a10 = v100 * (1.f - wx) + v101 * wx;
    float a11 = v110 * (1.f - wx) + v111 * wx;
    float b0 = a00 * (1.f - wy) + a01 * wy;
    float b1 = a10 * (1.f - wy) + a11 * wy;
    out[y * Wo + x + z * (Ho * Wo)] = b0 * (1.f - wz) + b1 * wz;
}

// ---------------------------------------------------------------------------
__device__ __forceinline__ float energy_lane(float duD, float duH, float duW,
                                             float dvD, float dvH, float dvW,
                                             float dwD, float dwH, float dwW,
                                             float giD, float giH, float giW)
{
    float Exx = duD, Eyy = dvH, Ezz = dwW;
    float Exy = 0.5f * (duH + dvD);
    float Exz = 0.5f * (duW + dwD);
    float Eyz = 0.5f * (dvW + dwH);
    float tr = Exx + Eyy + Ezz;
    float g = sqrtf(giD * giD + giH * giH + giW * giW);
    float lam = 1.0f + 0.5f * g;
    float mu  = 1.0f + 0.5f * g;
    float e = 0.5f * lam * tr * tr
            + mu * (Exx * Exx + Eyy * Eyy + Ezz * Ezz
                    + 2.0f * (Exy * Exy + Exz * Exz + Eyz * Eyz));
    return (1.0f + 0.1f * g) * e;
}

// ---------------------------------------------------------------------------
// 2.5D register-marching energy + reduction.
// Block (8,16): 32 W-floats x 16 H-rows; each thread marches DCH planes in D,
// carrying 3 D-planes per field in registers.
template<int D, int H, int W, int DCH>
__global__ void __launch_bounds__(128)
energy_kernel(const float* __restrict__ def, const float* __restrict__ img,
              int scale_idx)
{
    constexpr int Wq = W >> 2;
    constexpr int DCHUNKS = (D + DCH - 1) / DCH;
    constexpr int VOL = D * H * W;
    constexpr int sD = H * W;

    int xq = blockIdx.x * 8 + threadIdx.x;
    int h  = blockIdx.y * 16 + threadIdx.y;
    int zc = blockIdx.z;
    int n = 0, chunk = zc;
    if (zc >= DCHUNKS) { n = 1; chunk = zc - DCHUNKS; }
    int d0 = chunk * DCH;
    int dend = min(d0 + DCH, D);

    float local = 0.f;
    if (xq < Wq && h < H) {
        int w = xq << 2;
        const float* fp[4];
        fp[0] = def + (n * 3 + 0) * VOL;
        fp[1] = def + (n * 3 + 1) * VOL;
        fp[2] = def + (n * 3 + 2) * VOL;
        fp[3] = img + n * VOL;

        int rowOff = h * W + w;
        int hmOff  = (h > 0     ? h - 1 : h) * W + w;
        int hpOff  = (h < H - 1 ? h + 1 : h) * W + w;
        float sh = (h == 0 || h == H - 1) ? 1.f : 0.5f;

        float4 cprev[4], ccur[4], cnext[4];
        int dm0 = d0 > 0 ? d0 - 1 : 0;
        #pragma unroll
        for (int f = 0; f < 4; f++) {
            cprev[f] = *reinterpret_cast<const float4*>(fp[f] + dm0 * sD + rowOff);
            ccur[f]  = *reinterpret_cast<const float4*>(fp[f] + d0  * sD + rowOff);
        }

        for (int d = d0; d < dend; d++) {
            int dpn = d < D - 1 ? d + 1 : d;
            float sd = (d == 0 || d == D - 1) ? 1.f : 0.5f;

            float4 gD[4], gH[4], gW[4];
            #pragma unroll
            for (int f = 0; f < 4; f++) {
                const float* pd = fp[f] + d * sD;
                cnext[f] = *reinterpret_cast<const float4*>(fp[f] + dpn * sD + rowOff);
                float4 hmv = *reinterpret_cast<const float4*>(pd + hmOff);
                float4 hpv = *reinterpret_cast<const float4*>(pd + hpOff);

                gH[f].x = sh * (hpv.x - hmv.x);
                gH[f].y = sh * (hpv.y - hmv.y);
                gH[f].z = sh * (hpv.z - hmv.z);
                gH[f].w = sh * (hpv.w - hmv.w);

                gD[f].x = sd * (cnext[f].x - cprev[f].x);
                gD[f].y = sd * (cnext[f].y - cprev[f].y);
                gD[f].z = sd * (cnext[f].z - cprev[f].z);
                gD[f].w = sd * (cnext[f].w - cprev[f].w);

                float4 c = ccur[f];
                float xl = 0.f, xr = 0.f;
                if (w > 0)     xl = __ldg(pd + rowOff - 1);
                if (w + 4 < W) xr = __ldg(pd + rowOff + 4);
                gW[f].x = (w == 0)     ? (c.y - c.x) : 0.5f * (c.y - xl);
                gW[f].y = 0.5f * (c.z - c.x);
                gW[f].z = 0.5f * (c.w - c.y);
                gW[f].w = (w + 4 == W) ? (c.w - c.z) : 0.5f * (xr - c.z);
            }

            local += energy_lane(gD[0].x, gH[0].x, gW[0].x,
                                 gD[1].x, gH[1].x, gW[1].x,
                                 gD[2].x, gH[2].x, gW[2].x,
                                 gD[3].x, gH[3].x, gW[3].x);
            local += energy_lane(gD[0].y, gH[0].y, gW[0].y,
                                 gD[1].y, gH[1].y, gW[1].y,
                                 gD[2].y, gH[2].y, gW[2].y,
                                 gD[3].y, gH[3].y, gW[3].y);
            local += energy_lane(gD[0].z, gH[0].z, gW[0].z,
                                 gD[1].z, gH[1].z, gW[1].z,
                                 gD[2].z, gH[2].z, gW[2].z,
                                 gD[3].z, gH[3].z, gW[3].z);
            local += energy_lane(gD[0].w, gH[0].w, gW[0].w,
                                 gD[1].w, gH[1].w, gW[1].w,
                                 gD[2].w, gH[2].w, gW[2].w,
                                 gD[3].w, gH[3].w, gW[3].w);

            #pragma unroll
            for (int f = 0; f < 4; f++) { cprev[f] = ccur[f]; ccur[f] = cnext[f]; }
        }
    }

    // Block reduction (128 threads = 4 warps)
    #pragma unroll
    for (int o = 16; o > 0; o >>= 1)
        local += __shfl_down_sync(0xffffffffu, local, o);

    __shared__ float ws[4];
    int tid  = threadIdx.y * 8 + threadIdx.x;
    int lane = tid & 31;
    int wid  = tid >> 5;
    if (lane == 0) ws[wid] = local;
    __syncthreads();
    if (wid == 0) {
        float s = (lane < 4) ? ws[lane] : 0.f;
        #pragma unroll
        for (int o = 2; o > 0; o >>= 1)
            s += __shfl_down_sync(0xffffffffu, s, o);
        if (lane == 0)
            atomicAdd(&g_acc[scale_idx], (double)s);
    }
}

// ---------------------------------------------------------------------------
__global__ void finalize_kernel(float* out) {
    double m0 = g_acc[0] / (2.0 * VOL0);
    double m1 = g_acc[1] / (2.0 * VOL1);
    double m2 = g_acc[2] / (2.0 * VOL2);
    out[0] = (float)(m0 + m1 + m2);
}

// ---------------------------------------------------------------------------
extern "C" void kernel_launch(void* const* d_in, const int* in_sizes, int n_in,
                              void* d_out, int out_size)
{
    const float* def = (const float*)d_in[0];
    const float* img = (const float*)d_in[1];
    float* out = (float*)d_out;

    float *p_def1, *p_img1, *p_def2, *p_img2;
    cudaGetSymbolAddress((void**)&p_def1, g_def1);
    cudaGetSymbolAddress((void**)&p_img1, g_img1);
    cudaGetSymbolAddress((void**)&p_def2, g_def2);
    cudaGetSymbolAddress((void**)&p_img2, g_img2);

    init_acc_kernel<<<1, 32>>>();

    const dim3 eblk(8, 16);

    // ---- scale 0: full resolution ----
    {
        constexpr int DCHUNKS = (D0 + 15) / 16;
        dim3 grid(((W0 / 4) + 7) / 8, H0 / 16, 2 * DCHUNKS);
        energy_kernel<D0, H0, W0, 16><<<grid, eblk>>>(def, img, 0);
    }

    // ---- scale 1 ----
    {
        float rD = (float)((double)(D0 - 1) / (double)(D1 - 1));
        float rH = (float)((double)(H0 - 1) / (double)(H1 - 1));
        float rW = (float)((double)(W0 - 1) / (double)(W1 - 1));
        int total = 8 * VOL1;
        downsample_both<D0, H0, W0, D1, H1, W1>
            <<<(total + 255) / 256, 256>>>(def, img, p_def1, p_img1, rD, rH, rW);

        constexpr int DCHUNKS = (D1 + 15) / 16;
        dim3 grid(((W1 / 4) + 7) / 8, H1 / 16, 2 * DCHUNKS);
        energy_kernel<D1, H1, W1, 16><<<grid, eblk>>>(p_def1, p_img1, 1);
    }

    // ---- scale 2 ----
    {
        float rD = (float)((double)(D0 - 1) / (double)(D2 - 1));
        float rH = (float)((double)(H0 - 1) / (double)(H2 - 1));
        float rW = (float)((double)(W0 - 1) / (double)(W2 - 1));
        int total = 8 * VOL2;
        downsample_both<D0, H0, W0, D2, H2, W2>
            <<<(total + 255) / 256, 256>>>(def, img, p_def2, p_img2, rD, rH, rW);

        constexpr int DCHUNKS = (D2 + 15) / 16;
        dim3 grid(((W2 / 4) + 7) / 8, H2 / 16, 2 * DCHUNKS);
        energy_kernel<D2, H2, W2, 16><<<grid, eblk>>>(p_def2, p_img2, 2);
    }

    finalize_kernel<<<1, 1>>>(out);
}

// round 3
// speedup vs baseline: 1.4909x; 1.4909x over previous
#include <cuda_runtime.h>
#include <math.h>

// ---------------------------------------------------------------------------
// MultiScaleAdaptiveElasticityLossWithLame
//   d_in[0]: deformation_field (2,3,160,192,160) f32
//   d_in[1]: image             (2,1,160,192,160) f32
//   out: scalar f32 loss
// ---------------------------------------------------------------------------

#define D0 160
#define H0 192
#define W0 160
#define D1 80
#define H1 96
#define W1 80
#define D2 40
#define H2 48
#define W2 40

#define VOL0 (D0*H0*W0)
#define VOL1 (D1*H1*W1)
#define VOL2 (D2*H2*W2)

__device__ float g_def1[2*3*VOL1];
__device__ float g_img1[2*1*VOL1];
__device__ float g_def2[2*3*VOL2];
__device__ float g_img2[2*1*VOL2];
__device__ double g_acc[3];

__global__ void init_acc_kernel() {
    if (threadIdx.x < 3) g_acc[threadIdx.x] = 0.0;
}

// ---------------------------------------------------------------------------
// Fused trilinear downsample (align_corners=True): def (6 planes) + img (2).
template<int Di, int Hi, int Wi, int Do, int Ho, int Wo>
__global__ void downsample_both(const float* __restrict__ def,
                                const float* __restrict__ img,
                                float* __restrict__ odef,
                                float* __restrict__ oimg,
                                float rD, float rH, float rW)
{
    constexpr int OVOL = Do * Ho * Wo;
    constexpr int IVOL = Di * Hi * Wi;
    int idx = blockIdx.x * blockDim.x + threadIdx.x;
    if (idx >= 8 * OVOL) return;

    int x = idx % Wo; int t = idx / Wo;
    int y = t % Ho;   t /= Ho;
    int z = t % Do;   int p = t / Do;     // plane 0..7

    const float* in; float* out;
    if (p < 6) { in = def + p * IVOL;        out = odef + p * OVOL; }
    else       { in = img + (p - 6) * IVOL;  out = oimg + (p - 6) * OVOL; }

    float cz = (float)z * rD;
    float cy = (float)y * rH;
    float cx = (float)x * rW;
    int z0 = min((int)floorf(cz), Di - 1);
    int y0 = min((int)floorf(cy), Hi - 1);
    int x0 = min((int)floorf(cx), Wi - 1);
    float wz = cz - (float)z0;
    float wy = cy - (float)y0;
    float wx = cx - (float)x0;
    int z1 = min(z0 + 1, Di - 1);
    int y1 = min(y0 + 1, Hi - 1);
    int x1 = min(x0 + 1, Wi - 1);

    const float* pz0 = in + z0 * (Hi * Wi);
    const float* pz1 = in + z1 * (Hi * Wi);
    int oy0 = y0 * Wi, oy1 = y1 * Wi;

    float v000 = __ldg(pz0 + oy0 + x0), v001 = __ldg(pz0 + oy0 + x1);
    float v010 = __ldg(pz0 + oy1 + x0), v011 = __ldg(pz0 + oy1 + x1);
    float v100 = __ldg(pz1 + oy0 + x0), v101 = __ldg(pz1 + oy0 + x1);
    float v110 = __ldg(pz1 + oy1 + x0), v111 = __ldg(pz1 + oy1 + x1);

    float a00 = v000 * (1.f - wx) + v001 * wx;
    float a01 = v010 * (1.f - wx) + v011 * wx;
    float a10 = v100 * (1.f - wx) + v101 * wx;
    float a11 = v110 * (1.f - wx) + v111 * wx;
    float b0 = a00 * (1.f - wy) + a01 * wy;
    float b1 = a10 * (1.f - wy) + a11 * wy;
    out[y * Wo + x + z * (Ho * Wo)] = b0 * (1.f - wz) + b1 * wz;
}

// ---------------------------------------------------------------------------
__device__ __forceinline__ float energy_lane(float duD, float duH, float duW,
                                             float dvD, float dvH, float dvW,
                                             float dwD, float dwH, float dwW,
                                             float giD, float giH, float giW)
{
    float Exx = duD, Eyy = dvH, Ezz = dwW;
    float Exy = 0.5f * (duH + dvD);
    float Exz = 0.5f * (duW + dwD);
    float Eyz = 0.5f * (dvW + dwH);
    float tr = Exx + Eyy + Ezz;
    float g = sqrtf(giD * giD + giH * giH + giW * giW);
    float lam = 1.0f + 0.5f * g;
    float mu  = 1.0f + 0.5f * g;
    float e = 0.5f * lam * tr * tr
            + mu * (Exx * Exx + Eyy * Eyy + Ezz * Ezz
                    + 2.0f * (Exy * Exy + Exz * Exz + Eyz * Eyz));
    return (1.0f + 0.1f * g) * e;
}

// ---------------------------------------------------------------------------
// Scale-0: 2.5D register-marching energy. Block (8,16); each thread marches
// DCH planes in D carrying 3 planes/field in registers. hm/hp hit L1 (loaded
// as centers by same-block y-neighbors at the same step).
template<int D, int H, int W, int DCH>
__global__ void __launch_bounds__(128)
energy_march(const float* __restrict__ def, const float* __restrict__ img,
             int scale_idx)
{
    constexpr int Wq = W >> 2;
    constexpr int DCHUNKS = (D + DCH - 1) / DCH;
    constexpr int VOL = D * H * W;
    constexpr int sD = H * W;

    int xq = blockIdx.x * 8 + threadIdx.x;
    int h  = blockIdx.y * 16 + threadIdx.y;
    int zc = blockIdx.z;
    int n = 0, chunk = zc;
    if (zc >= DCHUNKS) { n = 1; chunk = zc - DCHUNKS; }
    int d0 = chunk * DCH;
    int dend = min(d0 + DCH, D);

    float local = 0.f;
    if (xq < Wq && h < H) {
        int w = xq << 2;
        const float* fp[4];
        fp[0] = def + (n * 3 + 0) * VOL;
        fp[1] = def + (n * 3 + 1) * VOL;
        fp[2] = def + (n * 3 + 2) * VOL;
        fp[3] = img + n * VOL;

        int rowOff = h * W + w;
        int hmOff  = (h > 0     ? h - 1 : h) * W + w;
        int hpOff  = (h < H - 1 ? h + 1 : h) * W + w;
        float sh = (h == 0 || h == H - 1) ? 1.f : 0.5f;

        float4 cprev[4], ccur[4], cnext[4];
        int dm0 = d0 > 0 ? d0 - 1 : 0;
        #pragma unroll
        for (int f = 0; f < 4; f++) {
            cprev[f] = *reinterpret_cast<const float4*>(fp[f] + dm0 * sD + rowOff);
            ccur[f]  = *reinterpret_cast<const float4*>(fp[f] + d0  * sD + rowOff);
        }

        for (int d = d0; d < dend; d++) {
            int dpn = d < D - 1 ? d + 1 : d;
            float sd = (d == 0 || d == D - 1) ? 1.f : 0.5f;

            float4 gD[4], gH[4], gW[4];
            #pragma unroll
            for (int f = 0; f < 4; f++) {
                const float* pd = fp[f] + d * sD;
                cnext[f] = *reinterpret_cast<const float4*>(fp[f] + dpn * sD + rowOff);
                float4 hmv = *reinterpret_cast<const float4*>(pd + hmOff);
                float4 hpv = *reinterpret_cast<const float4*>(pd + hpOff);

                gH[f].x = sh * (hpv.x - hmv.x);
                gH[f].y = sh * (hpv.y - hmv.y);
                gH[f].z = sh * (hpv.z - hmv.z);
                gH[f].w = sh * (hpv.w - hmv.w);

                gD[f].x = sd * (cnext[f].x - cprev[f].x);
                gD[f].y = sd * (cnext[f].y - cprev[f].y);
                gD[f].z = sd * (cnext[f].z - cprev[f].z);
                gD[f].w = sd * (cnext[f].w - cprev[f].w);

                float4 c = ccur[f];
                float xl = 0.f, xr = 0.f;
                if (w > 0)     xl = __ldg(pd + rowOff - 1);
                if (w + 4 < W) xr = __ldg(pd + rowOff + 4);
                gW[f].x = (w == 0)     ? (c.y - c.x) : 0.5f * (c.y - xl);
                gW[f].y = 0.5f * (c.z - c.x);
                gW[f].z = 0.5f * (c.w - c.y);
                gW[f].w = (w + 4 == W) ? (c.w - c.z) : 0.5f * (xr - c.z);
            }

            local += energy_lane(gD[0].x, gH[0].x, gW[0].x, gD[1].x, gH[1].x, gW[1].x,
                                 gD[2].x, gH[2].x, gW[2].x, gD[3].x, gH[3].x, gW[3].x);
            local += energy_lane(gD[0].y, gH[0].y, gW[0].y, gD[1].y, gH[1].y, gW[1].y,
                                 gD[2].y, gH[2].y, gW[2].y, gD[3].y, gH[3].y, gW[3].y);
            local += energy_lane(gD[0].z, gH[0].z, gW[0].z, gD[1].z, gH[1].z, gW[1].z,
                                 gD[2].z, gH[2].z, gW[2].z, gD[3].z, gH[3].z, gW[3].z);
            local += energy_lane(gD[0].w, gH[0].w, gW[0].w, gD[1].w, gH[1].w, gW[1].w,
                                 gD[2].w, gH[2].w, gW[2].w, gD[3].w, gH[3].w, gW[3].w);

            #pragma unroll
            for (int f = 0; f < 4; f++) { cprev[f] = ccur[f]; ccur[f] = cnext[f]; }
        }
    }

    #pragma unroll
    for (int o = 16; o > 0; o >>= 1)
        local += __shfl_down_sync(0xffffffffu, local, o);

    __shared__ float ws[4];
    int tid  = threadIdx.y * 8 + threadIdx.x;
    int lane = tid & 31;
    int wid  = tid >> 5;
    if (lane == 0) ws[wid] = local;
    __syncthreads();
    if (wid == 0) {
        float s = (lane < 4) ? ws[lane] : 0.f;
        #pragma unroll
        for (int o = 2; o > 0; o >>= 1)
            s += __shfl_down_sync(0xffffffffu, s, o);
        if (lane == 0)
            atomicAdd(&g_acc[scale_idx], (double)s);
    }
}

// ---------------------------------------------------------------------------
// Scales 1/2: flat one-thread-per-float4 energy (L2-resident, parallelism-first).
template<int D, int H, int W>
__device__ __forceinline__ void field_grads(const float* __restrict__ f,
                                            int d, int h, int w,
                                            float4& gD, float4& gH, float4& gW_)
{
    constexpr int sH = W;
    constexpr int sD = H * W;
    const float* base = f + d * sD + h * sH + w;

    float4 c = __ldg(reinterpret_cast<const float4*>(base));

    float xl = (w > 0)     ? __ldg(base - 1) : 0.f;
    float xr = (w + 4 < W) ? __ldg(base + 4) : 0.f;
    gW_.x = (w == 0)     ? (c.y - c.x) : 0.5f * (c.y - xl);
    gW_.y = 0.5f * (c.z - c.x);
    gW_.z = 0.5f * (c.w - c.y);
    gW_.w = (w + 4 == W) ? (c.w - c.z) : 0.5f * (xr - c.z);

    float4 hm = __ldg(reinterpret_cast<const float4*>(base - (h > 0     ? sH : 0)));
    float4 hp = __ldg(reinterpret_cast<const float4*>(base + (h < H - 1 ? sH : 0)));
    float sh = (h == 0 || h == H - 1) ? 1.0f : 0.5f;
    gH.x = sh * (hp.x - hm.x); gH.y = sh * (hp.y - hm.y);
    gH.z = sh * (hp.z - hm.z); gH.w = sh * (hp.w - hm.w);

    float4 dm = __ldg(reinterpret_cast<const float4*>(base - (d > 0     ? sD : 0)));
    float4 dp = __ldg(reinterpret_cast<const float4*>(base + (d < D - 1 ? sD : 0)));
    float sd = (d == 0 || d == D - 1) ? 1.0f : 0.5f;
    gD.x = sd * (dp.x - dm.x); gD.y = sd * (dp.y - dm.y);
    gD.z = sd * (dp.z - dm.z); gD.w = sd * (dp.w - dm.w);
}

template<int D, int H, int W>
__global__ void __launch_bounds__(256)
energy_flat(const float* __restrict__ def, const float* __restrict__ img,
            int scale_idx)
{
    constexpr int Wq = W >> 2;
    constexpr int TOTAL = 2 * D * H * Wq;
    constexpr int VOL = D * H * W;
    int i = blockIdx.x * 256 + threadIdx.x;

    float local = 0.f;
    if (i < TOTAL) {
        int xq = i % Wq; int t = i / Wq;
        int h = t % H;   t /= H;
        int d = t % D;
        int n = t / D;
        int w = xq << 2;

        const float* u  = def + (n * 3 + 0) * VOL;
        const float* v  = def + (n * 3 + 1) * VOL;
        const float* wf = def + (n * 3 + 2) * VOL;
        const float* ic = img + n * VOL;

        float4 uD, uH, uW, vD, vH, vW, wD, wH, wW, iD, iH, iW;
        field_grads<D, H, W>(u,  d, h, w, uD, uH, uW);
        field_grads<D, H, W>(v,  d, h, w, vD, vH, vW);
        field_grads<D, H, W>(wf, d, h, w, wD, wH, wW);
        field_grads<D, H, W>(ic, d, h, w, iD, iH, iW);

        local  = energy_lane(uD.x, uH.x, uW.x, vD.x, vH.x, vW.x, wD.x, wH.x, wW.x, iD.x, iH.x, iW.x);
        local += energy_lane(uD.y, uH.y, uW.y, vD.y, vH.y, vW.y, wD.y, wH.y, wW.y, iD.y, iH.y, iW.y);
        local += energy_lane(uD.z, uH.z, uW.z, vD.z, vH.z, vW.z, wD.z, wH.z, wW.z, iD.z, iH.z, iW.z);
        local += energy_lane(uD.w, uH.w, uW.w, vD.w, vH.w, vW.w, wD.w, wH.w, wW.w, iD.w, iH.w, iW.w);
    }

    #pragma unroll
    for (int o = 16; o > 0; o >>= 1)
        local += __shfl_down_sync(0xffffffffu, local, o);

    __shared__ float ws[8];
    int lane = threadIdx.x & 31;
    int wid  = threadIdx.x >> 5;
    if (lane == 0) ws[wid] = local;
    __syncthreads();
    if (wid == 0) {
        float s = (lane < 8) ? ws[lane] : 0.f;
        #pragma unroll
        for (int o = 4; o > 0; o >>= 1)
            s += __shfl_down_sync(0xffffffffu, s, o);
        if (lane == 0)
            atomicAdd(&g_acc[scale_idx], (double)s);
    }
}

// ---------------------------------------------------------------------------
__global__ void finalize_kernel(float* out) {
    double m0 = g_acc[0] / (2.0 * VOL0);
    double m1 = g_acc[1] / (2.0 * VOL1);
    double m2 = g_acc[2] / (2.0 * VOL2);
    out[0] = (float)(m0 + m1 + m2);
}

// ---------------------------------------------------------------------------
extern "C" void kernel_launch(void* const* d_in, const int* in_sizes, int n_in,
                              void* d_out, int out_size)
{
    const float* def = (const float*)d_in[0];
    const float* img = (const float*)d_in[1];
    float* out = (float*)d_out;

    float *p_def1, *p_img1, *p_def2, *p_img2;
    cudaGetSymbolAddress((void**)&p_def1, g_def1);
    cudaGetSymbolAddress((void**)&p_img1, g_img1);
    cudaGetSymbolAddress((void**)&p_def2, g_def2);
    cudaGetSymbolAddress((void**)&p_img2, g_img2);

    init_acc_kernel<<<1, 32>>>();

    // ---- scale 0: marching kernel, DCH=8 -> 2400 blocks ----
    {
        constexpr int DCH = 8;
        constexpr int DCHUNKS = (D0 + DCH - 1) / DCH;
        dim3 grid(((W0 / 4) + 7) / 8, H0 / 16, 2 * DCHUNKS);
        energy_march<D0, H0, W0, DCH><<<grid, dim3(8, 16)>>>(def, img, 0);
    }

    // ---- scale 1 ----
    {
        float rD = (float)((double)(D0 - 1) / (double)(D1 - 1));
        float rH = (float)((double)(H0 - 1) / (double)(H1 - 1));
        float rW = (float)((double)(W0 - 1) / (double)(W1 - 1));
        int total = 8 * VOL1;
        downsample_both<D0, H0, W0, D1, H1, W1>
            <<<(total + 255) / 256, 256>>>(def, img, p_def1, p_img1, rD, rH, rW);

        constexpr int T1 = 2 * D1 * H1 * (W1 / 4);
        energy_flat<D1, H1, W1><<<(T1 + 255) / 256, 256>>>(p_def1, p_img1, 1);
    }

    // ---- scale 2 ----
    {
        float rD = (float)((double)(D0 - 1) / (double)(D2 - 1));
        float rH = (float)((double)(H0 - 1) / (double)(H2 - 1));
        float rW = (float)((double)(W0 - 1) / (double)(W2 - 1));
        int total = 8 * VOL2;
        downsample_both<D0, H0, W0, D2, H2, W2>
            <<<(total + 255) / 256, 256>>>(def, img, p_def2, p_img2, rD, rH, rW);

        constexpr int T2 = 2 * D2 * H2 * (W2 / 4);
        energy_flat<D2, H2, W2><<<(T2 + 255) / 256, 256>>>(p_def2, p_img2, 2);
    }

    finalize_kernel<<<1, 1>>>(out);
}

// round 4
// speedup vs baseline: 2.0628x; 1.3836x over previous
#include <cuda_runtime.h>
#include <math.h>

// ---------------------------------------------------------------------------
// MultiScaleAdaptiveElasticityLossWithLame
//   d_in[0]: deformation_field (2,3,160,192,160) f32
//   d_in[1]: image             (2,1,160,192,160) f32
//   out: scalar f32 loss
// ---------------------------------------------------------------------------

#define D0 160
#define H0 192
#define W0 160
#define D1 80
#define H1 96
#define W1 80
#define D2 40
#define H2 48
#define W2 40

#define VOL0 (D0*H0*W0)
#define VOL1 (D1*H1*W1)
#define VOL2 (D2*H2*W2)

__device__ float g_def1[2*3*VOL1];
__device__ float g_img1[2*1*VOL1];
__device__ float g_def2[2*3*VOL2];
__device__ float g_img2[2*1*VOL2];
__device__ double g_acc[3];

__global__ void init_acc_kernel() {
    if (threadIdx.x < 3) g_acc[threadIdx.x] = 0.0;
}

// ---------------------------------------------------------------------------
// Trilinear downsample (align_corners=True), PLANES independent volumes.
template<int PLANES, int Di, int Hi, int Wi, int Do, int Ho, int Wo>
__global__ void __launch_bounds__(256)
downsample_kernel(const float* __restrict__ in, float* __restrict__ out,
                  float rD, float rH, float rW)
{
    constexpr int OVOL = Do * Ho * Wo;
    constexpr int IVOL = Di * Hi * Wi;
    int idx = blockIdx.x * 256 + threadIdx.x;
    if (idx >= PLANES * OVOL) return;

    int x = idx % Wo; int t = idx / Wo;
    int y = t % Ho;   t /= Ho;
    int z = t % Do;   int p = t / Do;

    const float* src = in + p * IVOL;

    float cz = (float)z * rD;
    float cy = (float)y * rH;
    float cx = (float)x * rW;
    int z0 = min((int)floorf(cz), Di - 1);
    int y0 = min((int)floorf(cy), Hi - 1);
    int x0 = min((int)floorf(cx), Wi - 1);
    float wz = cz - (float)z0;
    float wy = cy - (float)y0;
    float wx = cx - (float)x0;
    int z1 = min(z0 + 1, Di - 1);
    int y1 = min(y0 + 1, Hi - 1);
    int x1 = min(x0 + 1, Wi - 1);

    const float* pz0 = src + z0 * (Hi * Wi);
    const float* pz1 = src + z1 * (Hi * Wi);
    int oy0 = y0 * Wi, oy1 = y1 * Wi;

    float v000 = __ldg(pz0 + oy0 + x0), v001 = __ldg(pz0 + oy0 + x1);
    float v010 = __ldg(pz0 + oy1 + x0), v011 = __ldg(pz0 + oy1 + x1);
    float v100 = __ldg(pz1 + oy0 + x0), v101 = __ldg(pz1 + oy0 + x1);
    float v110 = __ldg(pz1 + oy1 + x0), v111 = __ldg(pz1 + oy1 + x1);

    float a00 = v000 * (1.f - wx) + v001 * wx;
    float a01 = v010 * (1.f - wx) + v011 * wx;
    float a10 = v100 * (1.f - wx) + v101 * wx;
    float a11 = v110 * (1.f - wx) + v111 * wx;
    float b0 = a00 * (1.f - wy) + a01 * wy;
    float b1 = a10 * (1.f - wy) + a11 * wy;
    out[idx] = b0 * (1.f - wz) + b1 * wz;
}

// ---------------------------------------------------------------------------
__device__ __forceinline__ float energy_lane(float duD, float duH, float duW,
                                             float dvD, float dvH, float dvW,
                                             float dwD, float dwH, float dwW,
                                             float giD, float giH, float giW)
{
    float Exx = duD, Eyy = dvH, Ezz = dwW;
    float Exy = 0.5f * (duH + dvD);
    float Exz = 0.5f * (duW + dwD);
    float Eyz = 0.5f * (dvW + dwH);
    float tr = Exx + Eyy + Ezz;
    float g = sqrtf(giD * giD + giH * giH + giW * giW);
    float lam = 1.0f + 0.5f * g;
    float mu  = 1.0f + 0.5f * g;
    float e = 0.5f * lam * tr * tr
            + mu * (Exx * Exx + Eyy * Eyy + Ezz * Ezz
                    + 2.0f * (Exy * Exy + Exz * Exz + Eyz * Eyz));
    return (1.0f + 0.1f * g) * e;
}

// ---------------------------------------------------------------------------
// torch.gradient of one field at 4 consecutive W positions.
template<int D, int H, int W>
__device__ __forceinline__ void field_grads(const float* __restrict__ f,
                                            int d, int h, int w,
                                            float4& gD, float4& gH, float4& gW_)
{
    constexpr int sH = W;
    constexpr int sD = H * W;
    const float* base = f + d * sD + h * sH + w;

    float4 c = __ldg(reinterpret_cast<const float4*>(base));

    float xl = (w > 0)     ? __ldg(base - 1) : 0.f;
    float xr = (w + 4 < W) ? __ldg(base + 4) : 0.f;
    gW_.x = (w == 0)     ? (c.y - c.x) : 0.5f * (c.y - xl);
    gW_.y = 0.5f * (c.z - c.x);
    gW_.z = 0.5f * (c.w - c.y);
    gW_.w = (w + 4 == W) ? (c.w - c.z) : 0.5f * (xr - c.z);

    float4 hm = __ldg(reinterpret_cast<const float4*>(base - (h > 0     ? sH : 0)));
    float4 hp = __ldg(reinterpret_cast<const float4*>(base + (h < H - 1 ? sH : 0)));
    float sh = (h == 0 || h == H - 1) ? 1.0f : 0.5f;
    gH.x = sh * (hp.x - hm.x); gH.y = sh * (hp.y - hm.y);
    gH.z = sh * (hp.z - hm.z); gH.w = sh * (hp.w - hm.w);

    float4 dm = __ldg(reinterpret_cast<const float4*>(base - (d > 0     ? sD : 0)));
    float4 dp = __ldg(reinterpret_cast<const float4*>(base + (d < D - 1 ? sD : 0)));
    float sd = (d == 0 || d == D - 1) ? 1.0f : 0.5f;
    gD.x = sd * (dp.x - dm.x); gD.y = sd * (dp.y - dm.y);
    gD.z = sd * (dp.z - dm.z); gD.w = sd * (dp.w - dm.w);
}

template<int D, int H, int W>
__global__ void __launch_bounds__(256)
energy_flat(const float* __restrict__ def, const float* __restrict__ img,
            int scale_idx)
{
    constexpr int Wq = W >> 2;
    constexpr int TOTAL = 2 * D * H * Wq;
    constexpr int VOL = D * H * W;
    int i = blockIdx.x * 256 + threadIdx.x;

    float local = 0.f;
    if (i < TOTAL) {
        int xq = i % Wq; int t = i / Wq;
        int h = t % H;   t /= H;
        int d = t % D;
        int n = t / D;
        int w = xq << 2;

        const float* u  = def + (n * 3 + 0) * VOL;
        const float* v  = def + (n * 3 + 1) * VOL;
        const float* wf = def + (n * 3 + 2) * VOL;
        const float* ic = img + n * VOL;

        float4 uD, uH, uW, vD, vH, vW, wD, wH, wW, iD, iH, iW;
        field_grads<D, H, W>(u,  d, h, w, uD, uH, uW);
        field_grads<D, H, W>(v,  d, h, w, vD, vH, vW);
        field_grads<D, H, W>(wf, d, h, w, wD, wH, wW);
        field_grads<D, H, W>(ic, d, h, w, iD, iH, iW);

        local  = energy_lane(uD.x, uH.x, uW.x, vD.x, vH.x, vW.x, wD.x, wH.x, wW.x, iD.x, iH.x, iW.x);
        local += energy_lane(uD.y, uH.y, uW.y, vD.y, vH.y, vW.y, wD.y, wH.y, wW.y, iD.y, iH.y, iW.y);
        local += energy_lane(uD.z, uH.z, uW.z, vD.z, vH.z, vW.z, wD.z, wH.z, wW.z, iD.z, iH.z, iW.z);
        local += energy_lane(uD.w, uH.w, uW.w, vD.w, vH.w, vW.w, wD.w, wH.w, wW.w, iD.w, iH.w, iW.w);
    }

    #pragma unroll
    for (int o = 16; o > 0; o >>= 1)
        local += __shfl_down_sync(0xffffffffu, local, o);

    __shared__ float ws[8];
    int lane = threadIdx.x & 31;
    int wid  = threadIdx.x >> 5;
    if (lane == 0) ws[wid] = local;
    __syncthreads();
    if (wid == 0) {
        float s = (lane < 8) ? ws[lane] : 0.f;
        #pragma unroll
        for (int o = 4; o > 0; o >>= 1)
            s += __shfl_down_sync(0xffffffffu, s, o);
        if (lane == 0)
            atomicAdd(&g_acc[scale_idx], (double)s);
    }
}

// ---------------------------------------------------------------------------
__global__ void finalize_kernel(float* out) {
    double m0 = g_acc[0] / (2.0 * VOL0);
    double m1 = g_acc[1] / (2.0 * VOL1);
    double m2 = g_acc[2] / (2.0 * VOL2);
    out[0] = (float)(m0 + m1 + m2);
}

// ---------------------------------------------------------------------------
extern "C" void kernel_launch(void* const* d_in, const int* in_sizes, int n_in,
                              void* d_out, int out_size)
{
    const float* def = (const float*)d_in[0];
    const float* img = (const float*)d_in[1];
    float* out = (float*)d_out;

    float *p_def1, *p_img1, *p_def2, *p_img2;
    cudaGetSymbolAddress((void**)&p_def1, g_def1);
    cudaGetSymbolAddress((void**)&p_img1, g_img1);
    cudaGetSymbolAddress((void**)&p_def2, g_def2);
    cudaGetSymbolAddress((void**)&p_img2, g_img2);

    init_acc_kernel<<<1, 32>>>();

    // ---- scale 0: flat energy over full volume ----
    {
        constexpr int T0 = 2 * D0 * H0 * (W0 / 4);
        energy_flat<D0, H0, W0><<<(T0 + 255) / 256, 256>>>(def, img, 0);
    }

    // ---- scale 1 ----
    {
        float rD = (float)((double)(D0 - 1) / (double)(D1 - 1));
        float rH = (float)((double)(H0 - 1) / (double)(H1 - 1));
        float rW = (float)((double)(W0 - 1) / (double)(W1 - 1));
        constexpr int TD = 6 * VOL1;
        downsample_kernel<6, D0, H0, W0, D1, H1, W1>
            <<<(TD + 255) / 256, 256>>>(def, p_def1, rD, rH, rW);
        constexpr int TI = 2 * VOL1;
        downsample_kernel<2, D0, H0, W0, D1, H1, W1>
            <<<(TI + 255) / 256, 256>>>(img, p_img1, rD, rH, rW);

        constexpr int T1 = 2 * D1 * H1 * (W1 / 4);
        energy_flat<D1, H1, W1><<<(T1 + 255) / 256, 256>>>(p_def1, p_img1, 1);
    }

    // ---- scale 2 ----
    {
        float rD = (float)((double)(D0 - 1) / (double)(D2 - 1));
        float rH = (float)((double)(H0 - 1) / (double)(H2 - 1));
        float rW = (float)((double)(W0 - 1) / (double)(W2 - 1));
        constexpr int TD = 6 * VOL2;
        downsample_kernel<6, D0, H0, W0, D2, H2, W2>
            <<<(TD + 255) / 256, 256>>>(def, p_def2, rD, rH, rW);
        constexpr int TI = 2 * VOL2;
        downsample_kernel<2, D0, H0, W0, D2, H2, W2>
            <<<(TI + 255) / 256, 256>>>(img, p_img2, rD, rH, rW);

        constexpr int T2 = 2 * D2 * H2 * (W2 / 4);
        energy_flat<D2, H2, W2><<<(T2 + 255) / 256, 256>>>(p_def2, p_img2, 2);
    }

    finalize_kernel<<<1, 1>>>(out);
}